// round 7
// baseline (speedup 1.0000x reference)
#include <cuda_runtime.h>
#include <math.h>

// x (2,3,384,384) f32, angles (2,180) f32 -> out (2,3,384,180) f32
// out[b][c][i][k] = sum_j bilinear(x[b,c], rot_k(i,j))
#define BB 2
#define CC 3
#define HH 384
#define WW 384
#define KK 180

#define TI 32
#define TJ 32
#define NTI (HH / TI)   // 12
#define NTJ (WW / TJ)   // 12

#define BOX 48          // bbox of 32x32 rotated tile + guard
#define PMIN 48
#define PMAX 55
#define PLANE (BOX * PMAX)   // plane stride (floats), P <= PMAX row stride inside

#define NTHREADS 256

__global__ __launch_bounds__(NTHREADS) void radon_fused_kernel(
    const float* __restrict__ x, const float* __restrict__ angles,
    float* __restrict__ out)
{
    __shared__ float sm[3 * PLANE];   // planar: ch0, ch1, ch2  (31.7 KB)

    const int ti = blockIdx.x;
    const int bk = blockIdx.y;        // b*KK + k
    const int b  = bk / KK;
    const int k  = bk - b * KK;
    const int i0 = ti * TI;

    const float theta = angles[bk] * (float)(M_PI / 180.0);
    float s, c;
    sincosf(theta, &s, &c);

    const float HC = 0.5f * (HH - 1);             // 191.5
    const float dix = s, djx = c;                  // d(fx)/di, d(fx)/dj
    const float diy = c, djy = -s;                 // d(fy)/di, d(fy)/dj

    const float* __restrict__ xb = x + (size_t)b * CC * HH * WW;
    const int HW = HH * WW;

    const int w = threadIdx.x >> 5;   // warp -> i row within group of 8
    const int l = threadIdx.x & 31;   // lane -> j within tile

    // ---- choose row stride P minimizing LDS bank conflicts for this angle ----
    // lane l's sampling word address ~ floor(y0 - l*s)*P + floor(x0 + l*c);
    // score each candidate P by exact max bank multiplicity across the warp.
    int bestP = PMIN, bestScore = 33;
    const float ly = 100.37f - (float)l * s;
    const float lx = 100.71f + (float)l * c;
    const int fy_r = __float2int_rd(ly);
    const int fx_r = __float2int_rd(lx);
    #pragma unroll
    for (int pc = PMIN; pc <= PMAX; pc++) {
        const int a = fy_r * pc + fx_r;
        const unsigned mask = __match_any_sync(0xffffffffu, a & 31);
        int deg = __popc(mask);
        #pragma unroll
        for (int off = 16; off > 0; off >>= 1)
            deg = max(deg, __shfl_xor_sync(0xffffffffu, deg, off));
        if (deg < bestScore) { bestScore = deg; bestP = pc; }
    }
    const int P = bestP;

    float acc[4][3];
    #pragma unroll
    for (int st = 0; st < 4; st++)
        #pragma unroll
        for (int ch = 0; ch < 3; ch++) acc[st][ch] = 0.f;

    for (int tj = 0; tj < NTJ; tj++) {
        const int j0 = tj * TJ;
        const float fx00 = HC + ((float)i0 - HC) * s + ((float)j0 - HC) * c;
        const float fy00 = HC + ((float)i0 - HC) * c - ((float)j0 - HC) * s;

        // tile is affine in (i,j): extremes at the 4 corners
        const float eI = (float)(TI - 1), eJ = (float)(TJ - 1);
        const float fxm = fminf(fminf(fx00, fx00 + eI * dix),
                                fminf(fx00 + eJ * djx, fx00 + eI * dix + eJ * djx));
        const float fym = fminf(fminf(fy00, fy00 + eI * diy),
                                fminf(fy00 + eJ * djy, fy00 + eI * diy + eJ * djy));
        const int xlo = (int)floorf(fxm) - 1;
        const int ylo = (int)floorf(fym) - 1;

        __syncthreads();   // previous tile's reads done before overwrite

        // ---- stage 48x48 box, planar, zero-filled outside image ----
        #pragma unroll
        for (int it = 0; it < (BOX * BOX) / NTHREADS; it++) {
            const int p  = threadIdx.x + it * NTHREADS;
            const int by = p / BOX;
            const int bx = p - by * BOX;
            const int gy = ylo + by;
            const int gx = xlo + bx;
            float v0 = 0.f, v1 = 0.f, v2 = 0.f;
            if ((unsigned)gy < (unsigned)HH && (unsigned)gx < (unsigned)WW) {
                const int o = gy * WW + gx;
                v0 = xb[o];
                v1 = xb[HW + o];
                v2 = xb[2 * HW + o];
            }
            const int si = by * P + bx;
            sm[si]             = v0;
            sm[PLANE + si]     = v1;
            sm[2 * PLANE + si] = v2;
        }
        __syncthreads();

        // ---- sample: warp w handles rows i0 + st*8 + w, lane l = j offset ----
        const float fxj = fx00 + (float)l * djx;
        const float fyj = fy00 + (float)l * djy;

        #pragma unroll
        for (int st = 0; st < 4; st++) {
            const float il = (float)(st * 8 + w);
            const float fx = fxj + il * dix;
            const float fy = fyj + il * diy;
            const int ix0 = __float2int_rd(fx);
            const int iy0 = __float2int_rd(fy);
            const float wx1 = fx - (float)ix0, wx0 = 1.f - wx1;
            const float wy1 = fy - (float)iy0, wy0 = 1.f - wy1;
            const int ix = ix0 - xlo;             // in [0,46]
            const int iy = iy0 - ylo;
            const int base = iy * P + ix;

            const float w00 = wy0 * wx0, w01 = wy0 * wx1;
            const float w10 = wy1 * wx0, w11 = wy1 * wx1;

            #pragma unroll
            for (int ch = 0; ch < 3; ch++) {
                const float* pl = sm + ch * PLANE + base;
                const float p00 = pl[0];
                const float p01 = pl[1];
                const float p10 = pl[P];
                const float p11 = pl[P + 1];
                acc[st][ch] = fmaf(p00, w00,
                              fmaf(p01, w01,
                              fmaf(p10, w10,
                              fmaf(p11, w11, acc[st][ch]))));
            }
        }
    }

    // ---- reduce over the 32 j-lanes and write out ----
    #pragma unroll
    for (int st = 0; st < 4; st++) {
        #pragma unroll
        for (int ch = 0; ch < 3; ch++) {
            float v = acc[st][ch];
            v += __shfl_xor_sync(0xffffffffu, v, 16);
            v += __shfl_xor_sync(0xffffffffu, v, 8);
            v += __shfl_xor_sync(0xffffffffu, v, 4);
            v += __shfl_xor_sync(0xffffffffu, v, 2);
            v += __shfl_xor_sync(0xffffffffu, v, 1);
            if (l == 0) {
                const int i = i0 + st * 8 + w;
                out[((b * CC + ch) * HH + i) * KK + k] = v;
            }
        }
    }
}

extern "C" void kernel_launch(void* const* d_in, const int* in_sizes, int n_in,
                              void* d_out, int out_size)
{
    const float* x = (const float*)d_in[0];       // (2,3,384,384)
    const float* angles = (const float*)d_in[1];  // (2,180)
    float* out = (float*)d_out;                   // (2,3,384,180)
    (void)in_sizes; (void)n_in; (void)out_size;

    dim3 grid(NTI, BB * KK);                      // 12 x 360 = 4320 blocks
    radon_fused_kernel<<<grid, NTHREADS>>>(x, angles, out);
}

// round 8
// speedup vs baseline: 1.0030x; 1.0030x over previous
#include <cuda_runtime.h>
#include <math.h>

// x (2,3,384,384) f32, angles (2,180) f32 -> out (2,3,384,180) f32
// out[b][c][i][k] = sum_j bilinear(x[b,c], rot_k(i,j))
#define BB 2
#define CC 3
#define HH 384
#define WW 384
#define KK 180

#define TI 32
#define TJ 32
#define NTI (HH / TI)   // 12
#define NTJ (WW / TJ)   // 12

#define BOX 48          // bbox of 32x32 rotated tile + guard
#define PMIN 48
#define PMAX 55
#define PLANE (BOX * PMAX)   // plane stride (floats), P <= PMAX row stride inside

#define NTHREADS 256

__global__ __launch_bounds__(NTHREADS) void radon_fused_kernel(
    const float* __restrict__ x, const float* __restrict__ angles,
    float* __restrict__ out)
{
    __shared__ float sm[3 * PLANE];   // planar: ch0, ch1, ch2  (31.7 KB)

    const int ti = blockIdx.x;
    const int bk = blockIdx.y;        // b*KK + k
    const int b  = bk / KK;
    const int k  = bk - b * KK;
    const int i0 = ti * TI;

    const float theta = angles[bk] * (float)(M_PI / 180.0);
    float s, c;
    sincosf(theta, &s, &c);

    const float HC = 0.5f * (HH - 1);             // 191.5
    const float dix = s, djx = c;                  // d(fx)/di, d(fx)/dj
    const float diy = c, djy = -s;                 // d(fy)/di, d(fy)/dj

    const float* __restrict__ xb = x + (size_t)b * CC * HH * WW;
    const int HW = HH * WW;

    const int w = threadIdx.x >> 5;   // warp -> i row within group of 8
    const int l = threadIdx.x & 31;   // lane -> j within tile

    // ---- choose row stride P minimizing LDS bank conflicts for this angle ----
    // lane l's sampling word address ~ floor(y0 - l*s)*P + floor(x0 + l*c);
    // score each candidate P by exact max bank multiplicity across the warp.
    int bestP = PMIN, bestScore = 33;
    const float ly = 100.37f - (float)l * s;
    const float lx = 100.71f + (float)l * c;
    const int fy_r = __float2int_rd(ly);
    const int fx_r = __float2int_rd(lx);
    #pragma unroll
    for (int pc = PMIN; pc <= PMAX; pc++) {
        const int a = fy_r * pc + fx_r;
        const unsigned mask = __match_any_sync(0xffffffffu, a & 31);
        int deg = __popc(mask);
        #pragma unroll
        for (int off = 16; off > 0; off >>= 1)
            deg = max(deg, __shfl_xor_sync(0xffffffffu, deg, off));
        if (deg < bestScore) { bestScore = deg; bestP = pc; }
    }
    const int P = bestP;

    float acc[4][3];
    #pragma unroll
    for (int st = 0; st < 4; st++)
        #pragma unroll
        for (int ch = 0; ch < 3; ch++) acc[st][ch] = 0.f;

    for (int tj = 0; tj < NTJ; tj++) {
        const int j0 = tj * TJ;
        const float fx00 = HC + ((float)i0 - HC) * s + ((float)j0 - HC) * c;
        const float fy00 = HC + ((float)i0 - HC) * c - ((float)j0 - HC) * s;

        // tile is affine in (i,j): extremes at the 4 corners
        const float eI = (float)(TI - 1), eJ = (float)(TJ - 1);
        const float fxm = fminf(fminf(fx00, fx00 + eI * dix),
                                fminf(fx00 + eJ * djx, fx00 + eI * dix + eJ * djx));
        const float fym = fminf(fminf(fy00, fy00 + eI * diy),
                                fminf(fy00 + eJ * djy, fy00 + eI * diy + eJ * djy));
        const int xlo = (int)floorf(fxm) - 1;
        const int ylo = (int)floorf(fym) - 1;

        __syncthreads();   // previous tile's reads done before overwrite

        // ---- stage 48x48 box, planar, zero-filled outside image ----
        #pragma unroll
        for (int it = 0; it < (BOX * BOX) / NTHREADS; it++) {
            const int p  = threadIdx.x + it * NTHREADS;
            const int by = p / BOX;
            const int bx = p - by * BOX;
            const int gy = ylo + by;
            const int gx = xlo + bx;
            float v0 = 0.f, v1 = 0.f, v2 = 0.f;
            if ((unsigned)gy < (unsigned)HH && (unsigned)gx < (unsigned)WW) {
                const int o = gy * WW + gx;
                v0 = xb[o];
                v1 = xb[HW + o];
                v2 = xb[2 * HW + o];
            }
            const int si = by * P + bx;
            sm[si]             = v0;
            sm[PLANE + si]     = v1;
            sm[2 * PLANE + si] = v2;
        }
        __syncthreads();

        // ---- sample: warp w handles rows i0 + st*8 + w, lane l = j offset ----
        const float fxj = fx00 + (float)l * djx;
        const float fyj = fy00 + (float)l * djy;

        #pragma unroll
        for (int st = 0; st < 4; st++) {
            const float il = (float)(st * 8 + w);
            const float fx = fxj + il * dix;
            const float fy = fyj + il * diy;
            const int ix0 = __float2int_rd(fx);
            const int iy0 = __float2int_rd(fy);
            const float wx1 = fx - (float)ix0, wx0 = 1.f - wx1;
            const float wy1 = fy - (float)iy0, wy0 = 1.f - wy1;
            const int ix = ix0 - xlo;             // in [0,46]
            const int iy = iy0 - ylo;
            const int base = iy * P + ix;

            const float w00 = wy0 * wx0, w01 = wy0 * wx1;
            const float w10 = wy1 * wx0, w11 = wy1 * wx1;

            #pragma unroll
            for (int ch = 0; ch < 3; ch++) {
                const float* pl = sm + ch * PLANE + base;
                const float p00 = pl[0];
                const float p01 = pl[1];
                const float p10 = pl[P];
                const float p11 = pl[P + 1];
                acc[st][ch] = fmaf(p00, w00,
                              fmaf(p01, w01,
                              fmaf(p10, w10,
                              fmaf(p11, w11, acc[st][ch]))));
            }
        }
    }

    // ---- reduce over the 32 j-lanes and write out ----
    #pragma unroll
    for (int st = 0; st < 4; st++) {
        #pragma unroll
        for (int ch = 0; ch < 3; ch++) {
            float v = acc[st][ch];
            v += __shfl_xor_sync(0xffffffffu, v, 16);
            v += __shfl_xor_sync(0xffffffffu, v, 8);
            v += __shfl_xor_sync(0xffffffffu, v, 4);
            v += __shfl_xor_sync(0xffffffffu, v, 2);
            v += __shfl_xor_sync(0xffffffffu, v, 1);
            if (l == 0) {
                const int i = i0 + st * 8 + w;
                out[((b * CC + ch) * HH + i) * KK + k] = v;
            }
        }
    }
}

extern "C" void kernel_launch(void* const* d_in, const int* in_sizes, int n_in,
                              void* d_out, int out_size)
{
    const float* x = (const float*)d_in[0];       // (2,3,384,384)
    const float* angles = (const float*)d_in[1];  // (2,180)
    float* out = (float*)d_out;                   // (2,3,384,180)
    (void)in_sizes; (void)n_in; (void)out_size;

    dim3 grid(NTI, BB * KK);                      // 12 x 360 = 4320 blocks
    radon_fused_kernel<<<grid, NTHREADS>>>(x, angles, out);
}

// round 9
// speedup vs baseline: 1.0052x; 1.0022x over previous
#include <cuda_runtime.h>
#include <math.h>

// x (2,3,384,384) f32, angles (2,180) f32 -> out (2,3,384,180) f32
// out[b][c][i][k] = sum_j bilinear(x[b,c], rot_k(i,j))
#define BB 2
#define CC 3
#define HH 384
#define WW 384
#define KK 180

#define TI 32
#define TJ 32
#define NTI (HH / TI)   // 12
#define NTJ (WW / TJ)   // 12

#define BOX 48          // bbox of 32x32 rotated tile + guard
#define PMIN 48
#define PMAX 55
#define PLANE (BOX * PMAX)   // plane stride (floats), P <= PMAX row stride inside

#define NTHREADS 256

__global__ __launch_bounds__(NTHREADS) void radon_fused_kernel(
    const float* __restrict__ x, const float* __restrict__ angles,
    float* __restrict__ out)
{
    __shared__ float sm[3 * PLANE];   // planar: ch0, ch1, ch2  (31.7 KB)

    const int ti = blockIdx.x;
    const int bk = blockIdx.y;        // b*KK + k
    const int b  = bk / KK;
    const int k  = bk - b * KK;
    const int i0 = ti * TI;

    const float theta = angles[bk] * (float)(M_PI / 180.0);
    float s, c;
    sincosf(theta, &s, &c);

    const float HC = 0.5f * (HH - 1);             // 191.5
    const float dix = s, djx = c;                  // d(fx)/di, d(fx)/dj
    const float diy = c, djy = -s;                 // d(fy)/di, d(fy)/dj

    const float* __restrict__ xb = x + (size_t)b * CC * HH * WW;
    const int HW = HH * WW;

    const int w = threadIdx.x >> 5;   // warp -> i row within group of 8
    const int l = threadIdx.x & 31;   // lane -> j within tile

    // ---- choose row stride P minimizing LDS bank conflicts for this angle ----
    // lane l's sampling word address ~ floor(y0 - l*s)*P + floor(x0 + l*c);
    // score each candidate P by exact max bank multiplicity across the warp.
    int bestP = PMIN, bestScore = 33;
    const float ly = 100.37f - (float)l * s;
    const float lx = 100.71f + (float)l * c;
    const int fy_r = __float2int_rd(ly);
    const int fx_r = __float2int_rd(lx);
    #pragma unroll
    for (int pc = PMIN; pc <= PMAX; pc++) {
        const int a = fy_r * pc + fx_r;
        const unsigned mask = __match_any_sync(0xffffffffu, a & 31);
        int deg = __popc(mask);
        #pragma unroll
        for (int off = 16; off > 0; off >>= 1)
            deg = max(deg, __shfl_xor_sync(0xffffffffu, deg, off));
        if (deg < bestScore) { bestScore = deg; bestP = pc; }
    }
    const int P = bestP;

    float acc[4][3];
    #pragma unroll
    for (int st = 0; st < 4; st++)
        #pragma unroll
        for (int ch = 0; ch < 3; ch++) acc[st][ch] = 0.f;

    for (int tj = 0; tj < NTJ; tj++) {
        const int j0 = tj * TJ;
        const float fx00 = HC + ((float)i0 - HC) * s + ((float)j0 - HC) * c;
        const float fy00 = HC + ((float)i0 - HC) * c - ((float)j0 - HC) * s;

        // tile is affine in (i,j): extremes at the 4 corners
        const float eI = (float)(TI - 1), eJ = (float)(TJ - 1);
        const float fxm = fminf(fminf(fx00, fx00 + eI * dix),
                                fminf(fx00 + eJ * djx, fx00 + eI * dix + eJ * djx));
        const float fym = fminf(fminf(fy00, fy00 + eI * diy),
                                fminf(fy00 + eJ * djy, fy00 + eI * diy + eJ * djy));
        const int xlo = (int)floorf(fxm) - 1;
        const int ylo = (int)floorf(fym) - 1;

        __syncthreads();   // previous tile's reads done before overwrite

        // ---- stage 48x48 box, planar, zero-filled outside image ----
        #pragma unroll
        for (int it = 0; it < (BOX * BOX) / NTHREADS; it++) {
            const int p  = threadIdx.x + it * NTHREADS;
            const int by = p / BOX;
            const int bx = p - by * BOX;
            const int gy = ylo + by;
            const int gx = xlo + bx;
            float v0 = 0.f, v1 = 0.f, v2 = 0.f;
            if ((unsigned)gy < (unsigned)HH && (unsigned)gx < (unsigned)WW) {
                const int o = gy * WW + gx;
                v0 = xb[o];
                v1 = xb[HW + o];
                v2 = xb[2 * HW + o];
            }
            const int si = by * P + bx;
            sm[si]             = v0;
            sm[PLANE + si]     = v1;
            sm[2 * PLANE + si] = v2;
        }
        __syncthreads();

        // ---- sample: warp w handles rows i0 + st*8 + w, lane l = j offset ----
        const float fxj = fx00 + (float)l * djx;
        const float fyj = fy00 + (float)l * djy;

        #pragma unroll
        for (int st = 0; st < 4; st++) {
            const float il = (float)(st * 8 + w);
            const float fx = fxj + il * dix;
            const float fy = fyj + il * diy;
            const int ix0 = __float2int_rd(fx);
            const int iy0 = __float2int_rd(fy);
            const float wx1 = fx - (float)ix0, wx0 = 1.f - wx1;
            const float wy1 = fy - (float)iy0, wy0 = 1.f - wy1;
            const int ix = ix0 - xlo;             // in [0,46]
            const int iy = iy0 - ylo;
            const int base = iy * P + ix;

            const float w00 = wy0 * wx0, w01 = wy0 * wx1;
            const float w10 = wy1 * wx0, w11 = wy1 * wx1;

            #pragma unroll
            for (int ch = 0; ch < 3; ch++) {
                const float* pl = sm + ch * PLANE + base;
                const float p00 = pl[0];
                const float p01 = pl[1];
                const float p10 = pl[P];
                const float p11 = pl[P + 1];
                acc[st][ch] = fmaf(p00, w00,
                              fmaf(p01, w01,
                              fmaf(p10, w10,
                              fmaf(p11, w11, acc[st][ch]))));
            }
        }
    }

    // ---- reduce over the 32 j-lanes and write out ----
    #pragma unroll
    for (int st = 0; st < 4; st++) {
        #pragma unroll
        for (int ch = 0; ch < 3; ch++) {
            float v = acc[st][ch];
            v += __shfl_xor_sync(0xffffffffu, v, 16);
            v += __shfl_xor_sync(0xffffffffu, v, 8);
            v += __shfl_xor_sync(0xffffffffu, v, 4);
            v += __shfl_xor_sync(0xffffffffu, v, 2);
            v += __shfl_xor_sync(0xffffffffu, v, 1);
            if (l == 0) {
                const int i = i0 + st * 8 + w;
                out[((b * CC + ch) * HH + i) * KK + k] = v;
            }
        }
    }
}

extern "C" void kernel_launch(void* const* d_in, const int* in_sizes, int n_in,
                              void* d_out, int out_size)
{
    const float* x = (const float*)d_in[0];       // (2,3,384,384)
    const float* angles = (const float*)d_in[1];  // (2,180)
    float* out = (float*)d_out;                   // (2,3,384,180)
    (void)in_sizes; (void)n_in; (void)out_size;

    dim3 grid(NTI, BB * KK);                      // 12 x 360 = 4320 blocks
    radon_fused_kernel<<<grid, NTHREADS>>>(x, angles, out);
}